// round 11
// baseline (speedup 1.0000x reference)
#include <cuda_runtime.h>
#include <cuda_bf16.h>
#include <cstdint>

#define T_STEPS 2048
#define BATCH   32
#define INDIM   512
#define HID     512
#define G4      2048   // 4*HID

typedef unsigned long long u64;

// packed f32x2 helpers
__device__ __forceinline__ u64 pk2(float x) {
    u64 r; asm("mov.b64 %0, {%1, %1};" : "=l"(r) : "f"(x)); return r;
}
__device__ __forceinline__ void ffma2(u64& d, u64 a, u64 b, u64 c) {
    asm("fma.rn.f32x2 %0, %1, %2, %3;" : "=l"(d) : "l"(a), "l"(b), "l"(c));
}
__device__ __forceinline__ void fadd2(u64& d, u64 a, u64 b) {
    asm("add.rn.f32x2 %0, %1, %2;" : "=l"(d) : "l"(a), "l"(b));
}
__device__ __forceinline__ float2 up2(u64 v) {
    float2 f; asm("mov.b64 {%0, %1}, %2;" : "=f"(f.x), "=f"(f.y) : "l"(v)); return f;
}
__device__ __forceinline__ float tanhfast(float x) {
    float r; asm("tanh.approx.f32 %0, %1;" : "=f"(r) : "f"(x)); return r;
}
__device__ __forceinline__ float sigfast(float x) {
    return fmaf(tanhfast(0.5f * x), 0.5f, 0.5f);
}

// bf16 mma m16n8k16 (row.col), fp32 accumulate
__device__ __forceinline__ void mma_bf16(float* c,
    uint32_t a0, uint32_t a1, uint32_t a2, uint32_t a3,
    uint32_t b0, uint32_t b1)
{
    asm volatile(
        "mma.sync.aligned.m16n8k16.row.col.f32.bf16.bf16.f32 "
        "{%0,%1,%2,%3},{%4,%5,%6,%7},{%8,%9},{%0,%1,%2,%3};"
        : "+f"(c[0]), "+f"(c[1]), "+f"(c[2]), "+f"(c[3])
        : "r"(a0), "r"(a1), "r"(a2), "r"(a3), "r"(b0), "r"(b1));
}

__device__ __forceinline__ uint32_t packbf(__nv_bfloat16 a, __nv_bfloat16 b) {
    __nv_bfloat162 p = __halves2bfloat162(a, b);
    return *reinterpret_cast<uint32_t*>(&p);
}
__device__ __forceinline__ int phiw(int w) {
    return (w & 8) | ((w & 3) << 1) | ((w >> 2) & 1);
}

// -------- persistent device scratch --------
__device__ float    g_xp[(size_t)T_STEPS * BATCH * G4];   // x_proj[t][b][g]
__device__ float    g_h2[2][2][HID * 16];                 // [dom][buf][k*16+b]
__device__ unsigned g_barD[2][4 * 32];                    // [dom][sub*32], 128B apart

// ============================================================================
// Kernel A (tensor, unchanged from R10): x_proj = seq @ W_ih^T + bias
// ============================================================================
__global__ __launch_bounds__(256) void xproj_tc_kernel(
    const float* __restrict__ seq,
    const float* __restrict__ Wih,
    const float* __restrict__ bih,
    const float* __restrict__ bhh)
{
    __shared__ uint32_t Ah[128 * 16];
    __shared__ uint32_t Al[128 * 16];
    __shared__ uint32_t Bh[64 * 16];
    __shared__ uint32_t Bl[64 * 16];

    const int tid  = threadIdx.x;
    const int lane = tid & 31;
    const int warp = tid >> 5;
    const int m0g  = blockIdx.y * 128;
    const int n0g  = blockIdx.x * 64;
    const int m0w  = (warp >> 1) * 32;
    const int n0w  = (warp & 1) * 32;
    const int q    = lane & 3;
    const int qr   = lane >> 2;

    float acc[2][4][4];
    #pragma unroll
    for (int i = 0; i < 2; ++i)
        #pragma unroll
        for (int j = 0; j < 4; ++j)
            #pragma unroll
            for (int v = 0; v < 4; ++v) acc[i][j][v] = 0.f;

    for (int kb = 0; kb < 512; kb += 32) {
        #pragma unroll
        for (int i = 0; i < 4; ++i) {
            int flat = tid + i * 256;
            int kq = flat & 7;
            int m  = flat >> 3;
            float4 v = *(const float4*)(seq + (size_t)(m0g + m) * 512 + kb + kq * 4);
            __nv_bfloat16 hx = __float2bfloat16_rn(v.x);
            __nv_bfloat16 hy = __float2bfloat16_rn(v.y);
            __nv_bfloat16 hz = __float2bfloat16_rn(v.z);
            __nv_bfloat16 hw = __float2bfloat16_rn(v.w);
            __nv_bfloat16 lx = __float2bfloat16_rn(v.x - __bfloat162float(hx));
            __nv_bfloat16 ly = __float2bfloat16_rn(v.y - __bfloat162float(hy));
            __nv_bfloat16 lz = __float2bfloat16_rn(v.z - __bfloat162float(hz));
            __nv_bfloat16 lw = __float2bfloat16_rn(v.w - __bfloat162float(hw));
            int sw = ((m >> 1) & 1) << 3;
            int p0 = m * 16 + (phiw(2 * kq    ) ^ sw);
            int p1 = m * 16 + (phiw(2 * kq + 1) ^ sw);
            Ah[p0] = packbf(hx, hy);  Al[p0] = packbf(lx, ly);
            Ah[p1] = packbf(hz, hw);  Al[p1] = packbf(lz, lw);
        }
        #pragma unroll
        for (int i = 0; i < 2; ++i) {
            int flat = tid + i * 256;
            int kq = flat & 7;
            int n  = flat >> 3;
            float4 v = *(const float4*)(Wih + (size_t)(n0g + n) * 512 + kb + kq * 4);
            __nv_bfloat16 hx = __float2bfloat16_rn(v.x);
            __nv_bfloat16 hy = __float2bfloat16_rn(v.y);
            __nv_bfloat16 hz = __float2bfloat16_rn(v.z);
            __nv_bfloat16 hw = __float2bfloat16_rn(v.w);
            __nv_bfloat16 lx = __float2bfloat16_rn(v.x - __bfloat162float(hx));
            __nv_bfloat16 ly = __float2bfloat16_rn(v.y - __bfloat162float(hy));
            __nv_bfloat16 lz = __float2bfloat16_rn(v.z - __bfloat162float(hz));
            __nv_bfloat16 lw = __float2bfloat16_rn(v.w - __bfloat162float(hw));
            int sw = ((n >> 1) & 1) << 3;
            int p0 = n * 16 + (phiw(2 * kq    ) ^ sw);
            int p1 = n * 16 + (phiw(2 * kq + 1) ^ sw);
            Bh[p0] = packbf(hx, hy);  Bl[p0] = packbf(lx, ly);
            Bh[p1] = packbf(hz, hw);  Bl[p1] = packbf(lz, lw);
        }
        __syncthreads();

        #pragma unroll
        for (int kt = 0; kt < 2; ++kt) {
            const int offBase = (kt << 3) | (q << 1);
            uint32_t ah[2][4], al[2][4];
            #pragma unroll
            for (int tm = 0; tm < 2; ++tm) {
                int r   = m0w + tm * 16 + qr;
                int off = offBase ^ (((r >> 1) & 1) << 3);
                u64 t0 = *(const u64*)(Ah + r * 16 + off);
                u64 t1 = *(const u64*)(Ah + (r + 8) * 16 + off);
                ah[tm][0] = (uint32_t)t0; ah[tm][2] = (uint32_t)(t0 >> 32);
                ah[tm][1] = (uint32_t)t1; ah[tm][3] = (uint32_t)(t1 >> 32);
                u64 s0 = *(const u64*)(Al + r * 16 + off);
                u64 s1 = *(const u64*)(Al + (r + 8) * 16 + off);
                al[tm][0] = (uint32_t)s0; al[tm][2] = (uint32_t)(s0 >> 32);
                al[tm][1] = (uint32_t)s1; al[tm][3] = (uint32_t)(s1 >> 32);
            }
            #pragma unroll
            for (int tn = 0; tn < 4; ++tn) {
                int rn   = n0w + tn * 8 + qr;
                int offb = offBase ^ (((rn >> 1) & 1) << 3);
                u64 hb = *(const u64*)(Bh + rn * 16 + offb);
                u64 lb = *(const u64*)(Bl + rn * 16 + offb);
                uint32_t bh0 = (uint32_t)hb, bh1 = (uint32_t)(hb >> 32);
                uint32_t bl0 = (uint32_t)lb, bl1 = (uint32_t)(lb >> 32);
                #pragma unroll
                for (int tm = 0; tm < 2; ++tm) {
                    mma_bf16(acc[tm][tn], ah[tm][0], ah[tm][1], ah[tm][2], ah[tm][3], bh0, bh1);
                    mma_bf16(acc[tm][tn], ah[tm][0], ah[tm][1], ah[tm][2], ah[tm][3], bl0, bl1);
                    mma_bf16(acc[tm][tn], al[tm][0], al[tm][1], al[tm][2], al[tm][3], bh0, bh1);
                }
            }
        }
        __syncthreads();
    }

    #pragma unroll
    for (int tn = 0; tn < 4; ++tn) {
        int c0 = n0g + n0w + tn * 8 + q * 2;
        float b0 = bih[c0]     + bhh[c0];
        float b1 = bih[c0 + 1] + bhh[c0 + 1];
        #pragma unroll
        for (int tm = 0; tm < 2; ++tm) {
            int row = m0g + m0w + tm * 16 + qr;
            float2 v0 = make_float2(acc[tm][tn][0] + b0, acc[tm][tn][1] + b1);
            float2 v1 = make_float2(acc[tm][tn][2] + b0, acc[tm][tn][3] + b1);
            __stcs((float2*)(g_xp + (size_t)row * 2048 + c0), v0);
            __stcs((float2*)(g_xp + (size_t)(row + 8) * 2048 + c0), v1);
        }
    }
}

// ============================================================================
// init: fill g_h2[dom][0] from h0, zero the 8 barrier counters
// ============================================================================
__global__ void init_kernel(const float* __restrict__ h0) {
    int i = blockIdx.x * 256 + threadIdx.x;     // 64 x 256 = 16384
    if (i < 2 * HID * 16) {
        int dom = i >> 13;
        int r   = i & 8191;
        int k   = r >> 4;
        int b   = r & 15;
        g_h2[dom][0][r] = h0[(dom * 16 + b) * 512 + k];
    }
    if (blockIdx.x == 0 && threadIdx.x < 8)
        g_barD[threadIdx.x >> 2][(threadIdx.x & 3) * 32] = 0u;
}

// ============================================================================
// Kernel B: persistent recurrence, 128 CTAs x 256 threads, TWO interleaved
//   batch-half sync domains per CTA. Each domain's barrier chain is covered
//   by the other domain's GEMM. CTA jc owns hidden units [4jc, 4jc+4).
//   Per-domain barrier: 4 sub-counters (by jc&3, 32 arrivals each).
// ============================================================================
__device__ __forceinline__ void rec_gemm(
    const float* __restrict__ wb, const float* __restrict__ hb,
    u64* __restrict__ Red, int gid, int rq, int bo)
{
    u64 acc[2][8];
    #pragma unroll
    for (int e = 0; e < 2; ++e)
        #pragma unroll
        for (int j = 0; j < 8; ++j) acc[e][j] = 0ull;

    #pragma unroll
    for (int kk = 0; kk < 16; ++kk) {
        ulonglong2 W2 = *(const ulonglong2*)(wb + kk * 16);
        float4 h0v = *(const float4*)(hb + kk * 16);
        float4 h1v = *(const float4*)(hb + kk * 16 + 4);
        u64 p0 = pk2(h0v.x), p1 = pk2(h0v.y), p2 = pk2(h0v.z), p3 = pk2(h0v.w);
        u64 p4 = pk2(h1v.x), p5 = pk2(h1v.y), p6 = pk2(h1v.z), p7 = pk2(h1v.w);
        ffma2(acc[0][0], W2.x, p0, acc[0][0]);
        ffma2(acc[0][1], W2.x, p1, acc[0][1]);
        ffma2(acc[0][2], W2.x, p2, acc[0][2]);
        ffma2(acc[0][3], W2.x, p3, acc[0][3]);
        ffma2(acc[0][4], W2.x, p4, acc[0][4]);
        ffma2(acc[0][5], W2.x, p5, acc[0][5]);
        ffma2(acc[0][6], W2.x, p6, acc[0][6]);
        ffma2(acc[0][7], W2.x, p7, acc[0][7]);
        ffma2(acc[1][0], W2.y, p0, acc[1][0]);
        ffma2(acc[1][1], W2.y, p1, acc[1][1]);
        ffma2(acc[1][2], W2.y, p2, acc[1][2]);
        ffma2(acc[1][3], W2.y, p3, acc[1][3]);
        ffma2(acc[1][4], W2.y, p4, acc[1][4]);
        ffma2(acc[1][5], W2.y, p5, acc[1][5]);
        ffma2(acc[1][6], W2.y, p6, acc[1][6]);
        ffma2(acc[1][7], W2.y, p7, acc[1][7]);
    }
    #pragma unroll
    for (int e = 0; e < 2; ++e)
        #pragma unroll
        for (int j = 0; j < 8; ++j)
            Red[(gid * 8 + rq * 2 + e) * 17 + bo * 8 + j] = acc[e][j];
}

__global__ __launch_bounds__(256) void lstm_rec_kernel(
    const float* __restrict__ h0,
    const float* __restrict__ c0,
    const float* __restrict__ Whh,
    float* __restrict__ out,
    long long out_size)
{
    extern __shared__ float sm[];
    float* Ws  = sm;                           // 512*16: [k][r], r = q*4+jl
    float* HsA = Ws  + 512 * 16;               // 512*16: [k][b]
    float* HsB = HsA + 512 * 16;               // 512*16
    u64*   Red = (u64*)(HsB + 512 * 16);       // 256 rows * 17
    float* Gs  = (float*)(Red + 256 * 17);     // 16 * 17

    const int tid = threadIdx.x;
    const int jc  = blockIdx.x;                // [0,128)
    const int jb  = jc * 4;

    // ---- one-time: W rows (r = q*4+jl) -> [k][16] SMEM ----
    for (int idx = tid; idx < 16 * 512; idx += 256) {
        int r = idx & 15, k = idx >> 4;
        int q = r >> 2, jl = r & 3;
        Ws[k * 16 + r] = Whh[((size_t)(q * 512 + jb + jl)) * 512 + k];
    }
    // ---- prologue: Hs from h0 (both domains), c into registers ----
    for (int idx = tid; idx < 512 * 16; idx += 256) {
        int b = idx & 15, k = idx >> 4;
        HsA[k * 16 + b] = h0[(b     ) * 512 + k];
        HsB[k * 16 + b] = h0[(b + 16) * 512 + k];
    }
    const int jl_c = tid & 3;
    const int b_c  = (tid >> 2) & 15;
    float cA = 0.f, cB = 0.f;
    if (tid < 64) {
        cA = c0[(b_c     ) * 512 + jb + jl_c];
        cB = c0[(b_c + 16) * 512 + jb + jl_c];
    }
    __syncthreads();

    const int gid = tid >> 3;          // 32 k-chunks of 16
    const int l8  = tid & 3;           // rq
    const int bo  = (tid >> 2) & 1;    // b-oct
    const int rq  = l8;
    const float* wb  = Ws  + gid * 256 + rq * 4;
    const float* hbA = HsA + gid * 256 + bo * 8;
    const float* hbB = HsB + gid * 256 + bo * 8;
    const int sub = jc & 3;

    const long long need = (long long)T_STEPS * BATCH * HID + 2LL * BATCH * HID;

    for (int t = 0; t < T_STEPS; ++t) {
        // xp prefetch for both domains (consumed in cell phases)
        float xa0=0.f, xa1=0.f, xa2=0.f, xa3=0.f;
        float xb0=0.f, xb1=0.f, xb2=0.f, xb3=0.f;
        if (tid < 64) {
            size_t baseA = ((size_t)t * 32 + b_c) * 2048 + jb + jl_c;
            xa0 = __ldcs(&g_xp[baseA]);
            xa1 = __ldcs(&g_xp[baseA + 512]);
            xa2 = __ldcs(&g_xp[baseA + 1024]);
            xa3 = __ldcs(&g_xp[baseA + 1536]);
            size_t baseB = baseA + (size_t)16 * 2048;
            xb0 = __ldcs(&g_xp[baseB]);
            xb1 = __ldcs(&g_xp[baseB + 512]);
            xb2 = __ldcs(&g_xp[baseB + 1024]);
            xb3 = __ldcs(&g_xp[baseB + 1536]);
        }

        // ================= PHASE 1: DOMAIN A compute =================
        rec_gemm(wb, hbA, Red, gid, rq, bo);
        __syncthreads();
        if (tid < 128) {
            int rp = tid >> 4, b = tid & 15;
            u64 s = Red[rp * 17 + b];
            #pragma unroll
            for (int g = 1; g < 32; ++g)
                fadd2(s, s, Red[(g * 8 + rp) * 17 + b]);
            float2 f = up2(s);
            Gs[(rp * 2    ) * 17 + b] = f.x;
            Gs[(rp * 2 + 1) * 17 + b] = f.y;
        }
        __syncthreads();
        if (tid < 64) {
            float zi = xa0 + Gs[(     jl_c) * 17 + b_c];
            float zf = xa1 + Gs[( 4 + jl_c) * 17 + b_c];
            float zg = xa2 + Gs[( 8 + jl_c) * 17 + b_c];
            float zo = xa3 + Gs[(12 + jl_c) * 17 + b_c];
            float ig = sigfast(zi);
            float fg = sigfast(zf);
            float gg = tanhfast(zg);
            float og = sigfast(zo);
            float cn = fg * cA + ig * gg;
            cA = cn;
            float hn = og * tanhfast(cn);
            g_h2[0][(t + 1) & 1][(jb + jl_c) * 16 + b_c] = hn;
            out[((size_t)t * 32 + b_c) * 512 + jb + jl_c] = hn;
            if (t == T_STEPS - 1 && out_size >= need) {
                size_t ob = (size_t)T_STEPS * BATCH * HID;
                out[ob + b_c * 512 + jb + jl_c]               = hn;
                out[ob + BATCH * HID + b_c * 512 + jb + jl_c] = cn;
            }
        }
        __threadfence();
        __syncthreads();
        if (t < T_STEPS - 1 && tid == 0)
            atomicAdd(&g_barD[0][sub * 32], 1u);

        // ======= PHASE 2: wait+stage DOMAIN B (covered by phase 1) =======
        if (t > 0) {
            if (tid < 4) {
                const volatile unsigned* c = &g_barD[1][tid * 32];
                const unsigned tgt = (unsigned)t * 32u;
                while (*c < tgt) { }
            }
            __syncthreads();
            const float* src = g_h2[1][t & 1];
            #pragma unroll
            for (int i = 0; i < 8; ++i) {
                int f = tid + i * 256;
                float4 v = __ldcg((const float4*)(src + f * 4));
                *(float4*)(HsB + f * 4) = v;
            }
            __syncthreads();
        }

        // ================= PHASE 3: DOMAIN B compute =================
        rec_gemm(wb, hbB, Red, gid, rq, bo);
        __syncthreads();
        if (tid < 128) {
            int rp = tid >> 4, b = tid & 15;
            u64 s = Red[rp * 17 + b];
            #pragma unroll
            for (int g = 1; g < 32; ++g)
                fadd2(s, s, Red[(g * 8 + rp) * 17 + b]);
            float2 f = up2(s);
            Gs[(rp * 2    ) * 17 + b] = f.x;
            Gs[(rp * 2 + 1) * 17 + b] = f.y;
        }
        __syncthreads();
        if (tid < 64) {
            float zi = xb0 + Gs[(     jl_c) * 17 + b_c];
            float zf = xb1 + Gs[( 4 + jl_c) * 17 + b_c];
            float zg = xb2 + Gs[( 8 + jl_c) * 17 + b_c];
            float zo = xb3 + Gs[(12 + jl_c) * 17 + b_c];
            float ig = sigfast(zi);
            float fg = sigfast(zf);
            float gg = tanhfast(zg);
            float og = sigfast(zo);
            float cn = fg * cB + ig * gg;
            cB = cn;
            float hn = og * tanhfast(cn);
            g_h2[1][(t + 1) & 1][(jb + jl_c) * 16 + b_c] = hn;
            out[((size_t)t * 32 + b_c + 16) * 512 + jb + jl_c] = hn;
            if (t == T_STEPS - 1 && out_size >= need) {
                size_t ob = (size_t)T_STEPS * BATCH * HID;
                out[ob + (b_c + 16) * 512 + jb + jl_c]               = hn;
                out[ob + BATCH * HID + (b_c + 16) * 512 + jb + jl_c] = cn;
            }
        }
        __threadfence();
        __syncthreads();
        if (t < T_STEPS - 1 && tid == 0)
            atomicAdd(&g_barD[1][sub * 32], 1u);

        // ======= PHASE 4: wait+stage DOMAIN A (covered by phase 3) =======
        if (t < T_STEPS - 1) {
            if (tid < 4) {
                const volatile unsigned* c = &g_barD[0][tid * 32];
                const unsigned tgt = (unsigned)(t + 1) * 32u;
                while (*c < tgt) { }
            }
            __syncthreads();
            const float* src = g_h2[0][(t + 1) & 1];
            #pragma unroll
            for (int i = 0; i < 8; ++i) {
                int f = tid + i * 256;
                float4 v = __ldcg((const float4*)(src + f * 4));
                *(float4*)(HsA + f * 4) = v;
            }
            __syncthreads();
        }
    }
}

// ============================================================================
extern "C" void kernel_launch(void* const* d_in, const int* in_sizes, int n_in,
                              void* d_out, int out_size)
{
    const float* seq = (const float*)d_in[0];
    const float* h0  = (const float*)d_in[1];
    const float* c0  = (const float*)d_in[2];
    const float* Wih = (const float*)d_in[3];
    const float* Whh = (const float*)d_in[4];
    const float* bih = (const float*)d_in[5];
    const float* bhh = (const float*)d_in[6];
    float* out = (float*)d_out;
    (void)in_sizes; (void)n_in;

    dim3 gA(2048 / 64, (T_STEPS * BATCH) / 128);   // (32, 512)
    xproj_tc_kernel<<<gA, 256>>>(seq, Wih, bih, bhh);

    init_kernel<<<64, 256>>>(h0);

    size_t smemB = (size_t)(3 * 512 * 16) * sizeof(float)   // Ws + HsA + HsB
                 + (size_t)(256 * 17) * sizeof(u64)         // Red
                 + (size_t)(16 * 17) * sizeof(float);       // Gs
    cudaFuncSetAttribute(lstm_rec_kernel,
                         cudaFuncAttributeMaxDynamicSharedMemorySize, (int)smemB);
    lstm_rec_kernel<<<128, 256, smemB>>>(h0, c0, Whh, out, (long long)out_size);
}

// round 13
// speedup vs baseline: 1.8679x; 1.8679x over previous
#include <cuda_runtime.h>
#include <cuda_bf16.h>
#include <cstdint>

#define T_STEPS 2048
#define BATCH   32
#define INDIM   512
#define HID     512
#define G4      2048   // 4*HID

typedef unsigned long long u64;

// packed f32x2 helpers
__device__ __forceinline__ u64 pk2(float x) {
    u64 r; asm("mov.b64 %0, {%1, %1};" : "=l"(r) : "f"(x)); return r;
}
__device__ __forceinline__ void ffma2(u64& d, u64 a, u64 b, u64 c) {
    asm("fma.rn.f32x2 %0, %1, %2, %3;" : "=l"(d) : "l"(a), "l"(b), "l"(c));
}
__device__ __forceinline__ void fadd2(u64& d, u64 a, u64 b) {
    asm("add.rn.f32x2 %0, %1, %2;" : "=l"(d) : "l"(a), "l"(b));
}
__device__ __forceinline__ float2 up2(u64 v) {
    float2 f; asm("mov.b64 {%0, %1}, %2;" : "=f"(f.x), "=f"(f.y) : "l"(v)); return f;
}
__device__ __forceinline__ float tanhfast(float x) {
    float r; asm("tanh.approx.f32 %0, %1;" : "=f"(r) : "f"(x)); return r;
}
__device__ __forceinline__ float sigfast(float x) {
    return fmaf(tanhfast(0.5f * x), 0.5f, 0.5f);
}

// bf16 mma m16n8k16 (row.col), fp32 accumulate
__device__ __forceinline__ void mma_bf16(float* c,
    uint32_t a0, uint32_t a1, uint32_t a2, uint32_t a3,
    uint32_t b0, uint32_t b1)
{
    asm volatile(
        "mma.sync.aligned.m16n8k16.row.col.f32.bf16.bf16.f32 "
        "{%0,%1,%2,%3},{%4,%5,%6,%7},{%8,%9},{%0,%1,%2,%3};"
        : "+f"(c[0]), "+f"(c[1]), "+f"(c[2]), "+f"(c[3])
        : "r"(a0), "r"(a1), "r"(a2), "r"(a3), "r"(b0), "r"(b1));
}

__device__ __forceinline__ uint32_t packbf(__nv_bfloat16 a, __nv_bfloat16 b) {
    __nv_bfloat162 p = __halves2bfloat162(a, b);
    return *reinterpret_cast<uint32_t*>(&p);
}
__device__ __forceinline__ int phiw(int w) {
    return (w & 8) | ((w & 3) << 1) | ((w >> 2) & 1);
}

// -------- persistent device scratch --------
__device__ float    g_xp[(size_t)T_STEPS * BATCH * G4];   // x_proj[t][b][g]
__device__ float    g_hT[2][HID * BATCH];                 // h transposed: [k][b]
__device__ unsigned g_bar2[2][32];                        // per-batch-group counters
// pre-split bf16 operands (k-pair words, row-major)
__device__ uint32_t g_seqH[(size_t)T_STEPS * BATCH * 256];
__device__ uint32_t g_seqL[(size_t)T_STEPS * BATCH * 256];
__device__ uint32_t g_WihH[(size_t)G4 * 256];
__device__ uint32_t g_WihL[(size_t)G4 * 256];

// ============================================================================
// conversion pre-passes: fp32 -> bf16 hi/lo k-pair words.
// NOTE: device scratch referenced directly (never pass __device__ symbols as
// host-side kernel args — the host shadow address is not the device address).
// ============================================================================
__device__ __forceinline__ void split_quad(float4 v, uint2& h, uint2& l) {
    __nv_bfloat16 hx = __float2bfloat16_rn(v.x);
    __nv_bfloat16 hy = __float2bfloat16_rn(v.y);
    __nv_bfloat16 hz = __float2bfloat16_rn(v.z);
    __nv_bfloat16 hw = __float2bfloat16_rn(v.w);
    __nv_bfloat16 lx = __float2bfloat16_rn(v.x - __bfloat162float(hx));
    __nv_bfloat16 ly = __float2bfloat16_rn(v.y - __bfloat162float(hy));
    __nv_bfloat16 lz = __float2bfloat16_rn(v.z - __bfloat162float(hz));
    __nv_bfloat16 lw = __float2bfloat16_rn(v.w - __bfloat162float(hw));
    h = make_uint2(packbf(hx, hy), packbf(hz, hw));
    l = make_uint2(packbf(lx, ly), packbf(lz, lw));
}

__global__ void conv_seq_kernel(const float* __restrict__ src) {
    long long i = (long long)blockIdx.x * blockDim.x + threadIdx.x;
    const long long nquads = (long long)T_STEPS * BATCH * 128;   // 512/4 per row
    if (i >= nquads) return;
    uint2 h, l;
    split_quad(((const float4*)src)[i], h, l);
    ((uint2*)g_seqH)[i] = h;
    ((uint2*)g_seqL)[i] = l;
}

__global__ void conv_wih_kernel(const float* __restrict__ src) {
    long long i = (long long)blockIdx.x * blockDim.x + threadIdx.x;
    const long long nquads = (long long)G4 * 128;
    if (i >= nquads) return;
    uint2 h, l;
    split_quad(((const float4*)src)[i], h, l);
    ((uint2*)g_WihH)[i] = h;
    ((uint2*)g_WihL)[i] = l;
}

// ============================================================================
// Kernel A (tensor): x_proj = seq @ W_ih^T + bias. Loads pre-split bf16.
// ============================================================================
__global__ __launch_bounds__(256) void xproj_tc_kernel(
    const float* __restrict__ bih,
    const float* __restrict__ bhh)
{
    __shared__ uint32_t Ah[128 * 16];
    __shared__ uint32_t Al[128 * 16];
    __shared__ uint32_t Bh[64 * 16];
    __shared__ uint32_t Bl[64 * 16];

    const int tid  = threadIdx.x;
    const int lane = tid & 31;
    const int warp = tid >> 5;
    const int m0g  = blockIdx.y * 128;
    const int n0g  = blockIdx.x * 64;
    const int m0w  = (warp >> 1) * 32;
    const int n0w  = (warp & 1) * 32;
    const int q    = lane & 3;
    const int qr   = lane >> 2;

    float acc[2][4][4];
    #pragma unroll
    for (int i = 0; i < 2; ++i)
        #pragma unroll
        for (int j = 0; j < 4; ++j)
            #pragma unroll
            for (int v = 0; v < 4; ++v) acc[i][j][v] = 0.f;

    for (int kb2 = 0; kb2 < 256; kb2 += 16) {       // k-pair offset (32 k / tile)
        // ---- A tile: 128 rows x 16 k-pair words, pure copy + swizzle ----
        #pragma unroll
        for (int i = 0; i < 4; ++i) {
            int flat = tid + i * 256;                // [0,1024)
            int kq = flat & 7;
            int m  = flat >> 3;
            size_t gw = (size_t)(m0g + m) * 256 + kb2 + kq * 2;
            uint2 h = *(const uint2*)(g_seqH + gw);
            uint2 l = *(const uint2*)(g_seqL + gw);
            int sw = ((m >> 1) & 1) << 3;
            int p0 = m * 16 + (phiw(2 * kq    ) ^ sw);
            int p1 = m * 16 + (phiw(2 * kq + 1) ^ sw);
            Ah[p0] = h.x;  Al[p0] = l.x;
            Ah[p1] = h.y;  Al[p1] = l.y;
        }
        // ---- B tile: 64 rows x 16 k-pair words ----
        #pragma unroll
        for (int i = 0; i < 2; ++i) {
            int flat = tid + i * 256;                // [0,512)
            int kq = flat & 7;
            int n  = flat >> 3;
            size_t gw = (size_t)(n0g + n) * 256 + kb2 + kq * 2;
            uint2 h = *(const uint2*)(g_WihH + gw);
            uint2 l = *(const uint2*)(g_WihL + gw);
            int sw = ((n >> 1) & 1) << 3;
            int p0 = n * 16 + (phiw(2 * kq    ) ^ sw);
            int p1 = n * 16 + (phiw(2 * kq + 1) ^ sw);
            Bh[p0] = h.x;  Bl[p0] = l.x;
            Bh[p1] = h.y;  Bl[p1] = l.y;
        }
        __syncthreads();

        #pragma unroll
        for (int kt = 0; kt < 2; ++kt) {
            const int offBase = (kt << 3) | (q << 1);
            uint32_t ah[2][4], al[2][4];
            #pragma unroll
            for (int tm = 0; tm < 2; ++tm) {
                int r   = m0w + tm * 16 + qr;
                int off = offBase ^ (((r >> 1) & 1) << 3);
                u64 t0 = *(const u64*)(Ah + r * 16 + off);
                u64 t1 = *(const u64*)(Ah + (r + 8) * 16 + off);
                ah[tm][0] = (uint32_t)t0; ah[tm][2] = (uint32_t)(t0 >> 32);
                ah[tm][1] = (uint32_t)t1; ah[tm][3] = (uint32_t)(t1 >> 32);
                u64 s0 = *(const u64*)(Al + r * 16 + off);
                u64 s1 = *(const u64*)(Al + (r + 8) * 16 + off);
                al[tm][0] = (uint32_t)s0; al[tm][2] = (uint32_t)(s0 >> 32);
                al[tm][1] = (uint32_t)s1; al[tm][3] = (uint32_t)(s1 >> 32);
            }
            #pragma unroll
            for (int tn = 0; tn < 4; ++tn) {
                int rn   = n0w + tn * 8 + qr;
                int offb = offBase ^ (((rn >> 1) & 1) << 3);
                u64 hb = *(const u64*)(Bh + rn * 16 + offb);
                u64 lb = *(const u64*)(Bl + rn * 16 + offb);
                uint32_t bh0 = (uint32_t)hb, bh1 = (uint32_t)(hb >> 32);
                uint32_t bl0 = (uint32_t)lb, bl1 = (uint32_t)(lb >> 32);
                #pragma unroll
                for (int tm = 0; tm < 2; ++tm) {
                    mma_bf16(acc[tm][tn], ah[tm][0], ah[tm][1], ah[tm][2], ah[tm][3], bh0, bh1);
                    mma_bf16(acc[tm][tn], ah[tm][0], ah[tm][1], ah[tm][2], ah[tm][3], bl0, bl1);
                    mma_bf16(acc[tm][tn], al[tm][0], al[tm][1], al[tm][2], al[tm][3], bh0, bh1);
                }
            }
        }
        __syncthreads();
    }

    #pragma unroll
    for (int tn = 0; tn < 4; ++tn) {
        int c0 = n0g + n0w + tn * 8 + q * 2;
        float b0 = bih[c0]     + bhh[c0];
        float b1 = bih[c0 + 1] + bhh[c0 + 1];
        #pragma unroll
        for (int tm = 0; tm < 2; ++tm) {
            int row = m0g + m0w + tm * 16 + qr;
            float2 v0 = make_float2(acc[tm][tn][0] + b0, acc[tm][tn][1] + b1);
            float2 v1 = make_float2(acc[tm][tn][2] + b0, acc[tm][tn][3] + b1);
            __stcs((float2*)(g_xp + (size_t)row * 2048 + c0), v0);
            __stcs((float2*)(g_xp + (size_t)(row + 8) * 2048 + c0), v1);
        }
    }
}

// ============================================================================
__global__ void reset_kernel() {
    if (threadIdx.x < 2) g_bar2[threadIdx.x][0] = 0u;
}

// ============================================================================
// Kernel B: persistent recurrence — EXACT R4/R10 structure (best measured).
// ============================================================================
__global__ __launch_bounds__(256) void lstm_rec_kernel(
    const float* __restrict__ h0,
    const float* __restrict__ c0,
    const float* __restrict__ Whh,
    float* __restrict__ out,
    long long out_size)
{
    extern __shared__ float sm[];
    float* Ws  = sm;                           // 512*32: [k][r], r^(((k>>5)&1)<<2)
    float* Hs  = Ws + 512 * 32;                // 512*32: [k][b], b^(((k>>5)&1)<<4)
    u64*   Red = (u64*)(Hs + 512 * 32);        // 16 groups * 16 r-pairs * 17
    float* Gs  = (float*)(Red + 16 * 16 * 17); // 512
    float* Cs  = Gs + 512;                     // 128

    const int tid = threadIdx.x;
    const int ct  = blockIdx.x;
    const int jg  = ct >> 1;
    const int bg  = ct & 1;
    const int jb  = jg * 8;
    const int bb  = bg * 16;

    for (int idx = tid; idx < 32 * 512; idx += 256) {
        int r = idx & 31, k = idx >> 5;
        int q = r >> 3, j = r & 7;
        float w = Whh[(size_t)(q * 512 + jb + j) * 512 + k];
        Ws[k * 32 + (r ^ (((k >> 5) & 1) << 2))] = w;
    }
    const int jj  = tid & 7;
    const int bbt = tid >> 3;
    if (tid < 128) Cs[bbt * 8 + jj] = c0[(bb + bbt) * 512 + jb + jj];
    for (int idx = tid; idx < 512 * 16; idx += 256) {
        int b = idx & 15, k = idx >> 4;
        Hs[k * 32 + (b ^ (((k >> 5) & 1) << 4))] = h0[(bb + b) * 512 + k];
    }
    __syncthreads();

    const int gid = tid >> 4;
    const int l16 = tid & 15;
    const int tm  = l16 & 3;
    const int tn  = l16 >> 2;
    const int cA  = (gid & 1) << 2;
    const int cH  = (gid & 1) << 4;
    const float* wsp = Ws + (size_t)gid * 32 * 32;
    const float* hsp = Hs + (size_t)gid * 32 * 32;
    const int aw0 = (tm * 8    ) ^ cA;
    const int aw1 = (tm * 8 + 4) ^ cA;
    const int hw  = (tn * 4    ) ^ cH;

    for (int t = 0; t < T_STEPS; ++t) {
        float xq0 = 0.f, xq1 = 0.f, xq2 = 0.f, xq3 = 0.f;
        if (tid < 128) {
            size_t base = ((size_t)t * 32 + bb + bbt) * 2048 + jb + jj;
            xq0 = __ldcs(&g_xp[base]);
            xq1 = __ldcs(&g_xp[base + 512]);
            xq2 = __ldcs(&g_xp[base + 1024]);
            xq3 = __ldcs(&g_xp[base + 1536]);
        }

        if (t > 0) {
            const float* hsrc = g_hT[t & 1];
            #pragma unroll
            for (int i = 0; i < 8; ++i) {
                int flat = tid + i * 256;
                int q  = flat & 3;
                int kr = flat >> 2;
                float4 v = __ldcg((const float4*)(hsrc + kr * 32 + bb + q * 4));
                *(float4*)(Hs + kr * 32 + ((q * 4) ^ (((kr >> 5) & 1) << 4))) = v;
            }
            __syncthreads();
        }

        u64 acc[4][4];
        #pragma unroll
        for (int i = 0; i < 4; ++i)
            #pragma unroll
            for (int j = 0; j < 4; ++j) acc[i][j] = 0ull;

        #pragma unroll 8
        for (int k = 0; k < 32; ++k) {
            ulonglong2 A0 = *(const ulonglong2*)(wsp + k * 32 + aw0);
            ulonglong2 A1 = *(const ulonglong2*)(wsp + k * 32 + aw1);
            float4 bv     = *(const float4*)    (hsp + k * 32 + hw);
            u64 b0 = pk2(bv.x), b1 = pk2(bv.y), b2 = pk2(bv.z), b3 = pk2(bv.w);
            ffma2(acc[0][0], A0.x, b0, acc[0][0]);
            ffma2(acc[0][1], A0.x, b1, acc[0][1]);
            ffma2(acc[0][2], A0.x, b2, acc[0][2]);
            ffma2(acc[0][3], A0.x, b3, acc[0][3]);
            ffma2(acc[1][0], A0.y, b0, acc[1][0]);
            ffma2(acc[1][1], A0.y, b1, acc[1][1]);
            ffma2(acc[1][2], A0.y, b2, acc[1][2]);
            ffma2(acc[1][3], A0.y, b3, acc[1][3]);
            ffma2(acc[2][0], A1.x, b0, acc[2][0]);
            ffma2(acc[2][1], A1.x, b1, acc[2][1]);
            ffma2(acc[2][2], A1.x, b2, acc[2][2]);
            ffma2(acc[2][3], A1.x, b3, acc[2][3]);
            ffma2(acc[3][0], A1.y, b0, acc[3][0]);
            ffma2(acc[3][1], A1.y, b1, acc[3][1]);
            ffma2(acc[3][2], A1.y, b2, acc[3][2]);
            ffma2(acc[3][3], A1.y, b3, acc[3][3]);
        }

        #pragma unroll
        for (int mp = 0; mp < 4; ++mp)
            #pragma unroll
            for (int n = 0; n < 4; ++n)
                Red[(gid * 16 + tm * 4 + mp) * 17 + (tn * 4 + n)] = acc[mp][n];
        __syncthreads();

        {
            int rp = tid >> 4, b = tid & 15;
            u64 s = Red[rp * 17 + b];
            #pragma unroll
            for (int g = 1; g < 16; ++g)
                fadd2(s, s, Red[(g * 16 + rp) * 17 + b]);
            float2 f = up2(s);
            Gs[(rp * 2    ) * 16 + b] = f.x;
            Gs[(rp * 2 + 1) * 16 + b] = f.y;
        }
        __syncthreads();

        if (tid < 128) {
            const int j = jj, b = bbt;
            float zi = xq0 + Gs[(     j) * 16 + b];
            float zf = xq1 + Gs[( 8 + j) * 16 + b];
            float zg = xq2 + Gs[(16 + j) * 16 + b];
            float zo = xq3 + Gs[(24 + j) * 16 + b];
            float ig = sigfast(zi);
            float fg = sigfast(zf);
            float gg = tanhfast(zg);
            float og = sigfast(zo);
            float cn = fg * Cs[b * 8 + j] + ig * gg;
            Cs[b * 8 + j] = cn;
            float hn = og * tanhfast(cn);

            g_hT[(t + 1) & 1][(jb + j) * 32 + bb + b] = hn;
            out[((size_t)t * 32 + bb + b) * 512 + jb + j] = hn;

            if (t == T_STEPS - 1) {
                long long need = (long long)T_STEPS * BATCH * HID + 2LL * BATCH * HID;
                if (out_size >= need) {
                    size_t ob = (size_t)T_STEPS * BATCH * HID;
                    out[ob + (bb + b) * 512 + jb + j]               = hn;
                    out[ob + BATCH * HID + (bb + b) * 512 + jb + j] = cn;
                }
            }
        }

        if (t < T_STEPS - 1) {
            __threadfence();
            __syncthreads();
            if (tid == 0) {
                atomicAdd(&g_bar2[bg][0], 1u);
                unsigned target = (unsigned)(t + 1) * 64u;
                while (*((volatile unsigned*)&g_bar2[bg][0]) < target) { }
            }
            __syncthreads();
        }
    }
}

// ============================================================================
extern "C" void kernel_launch(void* const* d_in, const int* in_sizes, int n_in,
                              void* d_out, int out_size)
{
    const float* seq = (const float*)d_in[0];
    const float* h0  = (const float*)d_in[1];
    const float* c0  = (const float*)d_in[2];
    const float* Wih = (const float*)d_in[3];
    const float* Whh = (const float*)d_in[4];
    const float* bih = (const float*)d_in[5];
    const float* bhh = (const float*)d_in[6];
    float* out = (float*)d_out;
    (void)in_sizes; (void)n_in;

    // pre-split conversion passes (device scratch referenced inside kernels)
    {
        long long quadsSeq = (long long)T_STEPS * BATCH * 128;   // 8,388,608
        conv_seq_kernel<<<(unsigned)((quadsSeq + 255) / 256), 256>>>(seq);
        long long quadsW = (long long)G4 * 128;                  // 262,144
        conv_wih_kernel<<<(unsigned)((quadsW + 255) / 256), 256>>>(Wih);
    }

    dim3 gA(2048 / 64, (T_STEPS * BATCH) / 128);   // (32, 512)
    xproj_tc_kernel<<<gA, 256>>>(bih, bhh);

    reset_kernel<<<1, 32>>>();

    size_t smem = (size_t)(512 * 32 + 512 * 32 + 512) * sizeof(float)
                + (size_t)(16 * 16 * 17) * sizeof(u64)
                + (size_t)128 * sizeof(float);
    cudaFuncSetAttribute(lstm_rec_kernel,
                         cudaFuncAttributeMaxDynamicSharedMemorySize, (int)smem);
    lstm_rec_kernel<<<128, 256, smem>>>(h0, c0, Whh, out, (long long)out_size);
}

// round 14
// speedup vs baseline: 1.8685x; 1.0003x over previous
#include <cuda_runtime.h>
#include <cuda_bf16.h>
#include <cstdint>

#define T_STEPS 2048
#define BATCH   32
#define INDIM   512
#define HID     512
#define G4      2048   // 4*HID

typedef unsigned long long u64;

// packed f32x2 helpers
__device__ __forceinline__ u64 pk2(float x) {
    u64 r; asm("mov.b64 %0, {%1, %1};" : "=l"(r) : "f"(x)); return r;
}
__device__ __forceinline__ void ffma2(u64& d, u64 a, u64 b, u64 c) {
    asm("fma.rn.f32x2 %0, %1, %2, %3;" : "=l"(d) : "l"(a), "l"(b), "l"(c));
}
__device__ __forceinline__ void fadd2(u64& d, u64 a, u64 b) {
    asm("add.rn.f32x2 %0, %1, %2;" : "=l"(d) : "l"(a), "l"(b));
}
__device__ __forceinline__ float2 up2(u64 v) {
    float2 f; asm("mov.b64 {%0, %1}, %2;" : "=f"(f.x), "=f"(f.y) : "l"(v)); return f;
}
__device__ __forceinline__ float tanhfast(float x) {
    float r; asm("tanh.approx.f32 %0, %1;" : "=f"(r) : "f"(x)); return r;
}
__device__ __forceinline__ float sigfast(float x) {
    return fmaf(tanhfast(0.5f * x), 0.5f, 0.5f);
}

// bf16 mma m16n8k16 (row.col), fp32 accumulate
__device__ __forceinline__ void mma_bf16(float* c,
    uint32_t a0, uint32_t a1, uint32_t a2, uint32_t a3,
    uint32_t b0, uint32_t b1)
{
    asm volatile(
        "mma.sync.aligned.m16n8k16.row.col.f32.bf16.bf16.f32 "
        "{%0,%1,%2,%3},{%4,%5,%6,%7},{%8,%9},{%0,%1,%2,%3};"
        : "+f"(c[0]), "+f"(c[1]), "+f"(c[2]), "+f"(c[3])
        : "r"(a0), "r"(a1), "r"(a2), "r"(a3), "r"(b0), "r"(b1));
}

__device__ __forceinline__ uint32_t packbf(__nv_bfloat16 a, __nv_bfloat16 b) {
    __nv_bfloat162 p = __halves2bfloat162(a, b);
    return *reinterpret_cast<uint32_t*>(&p);
}
__device__ __forceinline__ int phiw(int w) {
    return (w & 8) | ((w & 3) << 1) | ((w >> 2) & 1);
}

// -------- persistent device scratch --------
__device__ float    g_xp[(size_t)T_STEPS * BATCH * G4];   // x_proj[t][b][g]
__device__ float    g_hT[2][HID * BATCH];                 // h transposed: [k][b]
__device__ unsigned g_bar2[2][32];                        // per-batch-group counters
// pre-split bf16 operands (k-pair words, row-major)
__device__ uint32_t g_seqH[(size_t)T_STEPS * BATCH * 256];
__device__ uint32_t g_seqL[(size_t)T_STEPS * BATCH * 256];
__device__ uint32_t g_WihH[(size_t)G4 * 256];
__device__ uint32_t g_WihL[(size_t)G4 * 256];

// ============================================================================
// conversion pre-passes: fp32 -> bf16 hi/lo k-pair words.
// NOTE: device scratch referenced directly (never pass __device__ symbols as
// host-side kernel args — the host shadow address is not the device address).
// ============================================================================
__device__ __forceinline__ void split_quad(float4 v, uint2& h, uint2& l) {
    __nv_bfloat16 hx = __float2bfloat16_rn(v.x);
    __nv_bfloat16 hy = __float2bfloat16_rn(v.y);
    __nv_bfloat16 hz = __float2bfloat16_rn(v.z);
    __nv_bfloat16 hw = __float2bfloat16_rn(v.w);
    __nv_bfloat16 lx = __float2bfloat16_rn(v.x - __bfloat162float(hx));
    __nv_bfloat16 ly = __float2bfloat16_rn(v.y - __bfloat162float(hy));
    __nv_bfloat16 lz = __float2bfloat16_rn(v.z - __bfloat162float(hz));
    __nv_bfloat16 lw = __float2bfloat16_rn(v.w - __bfloat162float(hw));
    h = make_uint2(packbf(hx, hy), packbf(hz, hw));
    l = make_uint2(packbf(lx, ly), packbf(lz, lw));
}

__global__ void conv_seq_kernel(const float* __restrict__ src) {
    long long i = (long long)blockIdx.x * blockDim.x + threadIdx.x;
    const long long nquads = (long long)T_STEPS * BATCH * 128;   // 512/4 per row
    if (i >= nquads) return;
    uint2 h, l;
    split_quad(((const float4*)src)[i], h, l);
    ((uint2*)g_seqH)[i] = h;
    ((uint2*)g_seqL)[i] = l;
}

__global__ void conv_wih_kernel(const float* __restrict__ src) {
    long long i = (long long)blockIdx.x * blockDim.x + threadIdx.x;
    const long long nquads = (long long)G4 * 128;
    if (i >= nquads) return;
    uint2 h, l;
    split_quad(((const float4*)src)[i], h, l);
    ((uint2*)g_WihH)[i] = h;
    ((uint2*)g_WihL)[i] = l;
}

// ============================================================================
// Kernel A (tensor): x_proj = seq @ W_ih^T + bias. Loads pre-split bf16.
// ============================================================================
__global__ __launch_bounds__(256) void xproj_tc_kernel(
    const float* __restrict__ bih,
    const float* __restrict__ bhh)
{
    __shared__ uint32_t Ah[128 * 16];
    __shared__ uint32_t Al[128 * 16];
    __shared__ uint32_t Bh[64 * 16];
    __shared__ uint32_t Bl[64 * 16];

    const int tid  = threadIdx.x;
    const int lane = tid & 31;
    const int warp = tid >> 5;
    const int m0g  = blockIdx.y * 128;
    const int n0g  = blockIdx.x * 64;
    const int m0w  = (warp >> 1) * 32;
    const int n0w  = (warp & 1) * 32;
    const int q    = lane & 3;
    const int qr   = lane >> 2;

    float acc[2][4][4];
    #pragma unroll
    for (int i = 0; i < 2; ++i)
        #pragma unroll
        for (int j = 0; j < 4; ++j)
            #pragma unroll
            for (int v = 0; v < 4; ++v) acc[i][j][v] = 0.f;

    for (int kb2 = 0; kb2 < 256; kb2 += 16) {       // k-pair offset (32 k / tile)
        // ---- A tile: 128 rows x 16 k-pair words, pure copy + swizzle ----
        #pragma unroll
        for (int i = 0; i < 4; ++i) {
            int flat = tid + i * 256;                // [0,1024)
            int kq = flat & 7;
            int m  = flat >> 3;
            size_t gw = (size_t)(m0g + m) * 256 + kb2 + kq * 2;
            uint2 h = *(const uint2*)(g_seqH + gw);
            uint2 l = *(const uint2*)(g_seqL + gw);
            int sw = ((m >> 1) & 1) << 3;
            int p0 = m * 16 + (phiw(2 * kq    ) ^ sw);
            int p1 = m * 16 + (phiw(2 * kq + 1) ^ sw);
            Ah[p0] = h.x;  Al[p0] = l.x;
            Ah[p1] = h.y;  Al[p1] = l.y;
        }
        // ---- B tile: 64 rows x 16 k-pair words ----
        #pragma unroll
        for (int i = 0; i < 2; ++i) {
            int flat = tid + i * 256;                // [0,512)
            int kq = flat & 7;
            int n  = flat >> 3;
            size_t gw = (size_t)(n0g + n) * 256 + kb2 + kq * 2;
            uint2 h = *(const uint2*)(g_WihH + gw);
            uint2 l = *(const uint2*)(g_WihL + gw);
            int sw = ((n >> 1) & 1) << 3;
            int p0 = n * 16 + (phiw(2 * kq    ) ^ sw);
            int p1 = n * 16 + (phiw(2 * kq + 1) ^ sw);
            Bh[p0] = h.x;  Bl[p0] = l.x;
            Bh[p1] = h.y;  Bl[p1] = l.y;
        }
        __syncthreads();

        #pragma unroll
        for (int kt = 0; kt < 2; ++kt) {
            const int offBase = (kt << 3) | (q << 1);
            uint32_t ah[2][4], al[2][4];
            #pragma unroll
            for (int tm = 0; tm < 2; ++tm) {
                int r   = m0w + tm * 16 + qr;
                int off = offBase ^ (((r >> 1) & 1) << 3);
                u64 t0 = *(const u64*)(Ah + r * 16 + off);
                u64 t1 = *(const u64*)(Ah + (r + 8) * 16 + off);
                ah[tm][0] = (uint32_t)t0; ah[tm][2] = (uint32_t)(t0 >> 32);
                ah[tm][1] = (uint32_t)t1; ah[tm][3] = (uint32_t)(t1 >> 32);
                u64 s0 = *(const u64*)(Al + r * 16 + off);
                u64 s1 = *(const u64*)(Al + (r + 8) * 16 + off);
                al[tm][0] = (uint32_t)s0; al[tm][2] = (uint32_t)(s0 >> 32);
                al[tm][1] = (uint32_t)s1; al[tm][3] = (uint32_t)(s1 >> 32);
            }
            #pragma unroll
            for (int tn = 0; tn < 4; ++tn) {
                int rn   = n0w + tn * 8 + qr;
                int offb = offBase ^ (((rn >> 1) & 1) << 3);
                u64 hb = *(const u64*)(Bh + rn * 16 + offb);
                u64 lb = *(const u64*)(Bl + rn * 16 + offb);
                uint32_t bh0 = (uint32_t)hb, bh1 = (uint32_t)(hb >> 32);
                uint32_t bl0 = (uint32_t)lb, bl1 = (uint32_t)(lb >> 32);
                #pragma unroll
                for (int tm = 0; tm < 2; ++tm) {
                    mma_bf16(acc[tm][tn], ah[tm][0], ah[tm][1], ah[tm][2], ah[tm][3], bh0, bh1);
                    mma_bf16(acc[tm][tn], ah[tm][0], ah[tm][1], ah[tm][2], ah[tm][3], bl0, bl1);
                    mma_bf16(acc[tm][tn], al[tm][0], al[tm][1], al[tm][2], al[tm][3], bh0, bh1);
                }
            }
        }
        __syncthreads();
    }

    #pragma unroll
    for (int tn = 0; tn < 4; ++tn) {
        int c0 = n0g + n0w + tn * 8 + q * 2;
        float b0 = bih[c0]     + bhh[c0];
        float b1 = bih[c0 + 1] + bhh[c0 + 1];
        #pragma unroll
        for (int tm = 0; tm < 2; ++tm) {
            int row = m0g + m0w + tm * 16 + qr;
            float2 v0 = make_float2(acc[tm][tn][0] + b0, acc[tm][tn][1] + b1);
            float2 v1 = make_float2(acc[tm][tn][2] + b0, acc[tm][tn][3] + b1);
            __stcs((float2*)(g_xp + (size_t)row * 2048 + c0), v0);
            __stcs((float2*)(g_xp + (size_t)(row + 8) * 2048 + c0), v1);
        }
    }
}

// ============================================================================
__global__ void reset_kernel() {
    if (threadIdx.x < 2) g_bar2[threadIdx.x][0] = 0u;
}

// ============================================================================
// Kernel B: persistent recurrence — EXACT R4/R10 structure (best measured).
// ============================================================================
__global__ __launch_bounds__(256) void lstm_rec_kernel(
    const float* __restrict__ h0,
    const float* __restrict__ c0,
    const float* __restrict__ Whh,
    float* __restrict__ out,
    long long out_size)
{
    extern __shared__ float sm[];
    float* Ws  = sm;                           // 512*32: [k][r], r^(((k>>5)&1)<<2)
    float* Hs  = Ws + 512 * 32;                // 512*32: [k][b], b^(((k>>5)&1)<<4)
    u64*   Red = (u64*)(Hs + 512 * 32);        // 16 groups * 16 r-pairs * 17
    float* Gs  = (float*)(Red + 16 * 16 * 17); // 512
    float* Cs  = Gs + 512;                     // 128

    const int tid = threadIdx.x;
    const int ct  = blockIdx.x;
    const int jg  = ct >> 1;
    const int bg  = ct & 1;
    const int jb  = jg * 8;
    const int bb  = bg * 16;

    for (int idx = tid; idx < 32 * 512; idx += 256) {
        int r = idx & 31, k = idx >> 5;
        int q = r >> 3, j = r & 7;
        float w = Whh[(size_t)(q * 512 + jb + j) * 512 + k];
        Ws[k * 32 + (r ^ (((k >> 5) & 1) << 2))] = w;
    }
    const int jj  = tid & 7;
    const int bbt = tid >> 3;
    if (tid < 128) Cs[bbt * 8 + jj] = c0[(bb + bbt) * 512 + jb + jj];
    for (int idx = tid; idx < 512 * 16; idx += 256) {
        int b = idx & 15, k = idx >> 4;
        Hs[k * 32 + (b ^ (((k >> 5) & 1) << 4))] = h0[(bb + b) * 512 + k];
    }
    __syncthreads();

    const int gid = tid >> 4;
    const int l16 = tid & 15;
    const int tm  = l16 & 3;
    const int tn  = l16 >> 2;
    const int cA  = (gid & 1) << 2;
    const int cH  = (gid & 1) << 4;
    const float* wsp = Ws + (size_t)gid * 32 * 32;
    const float* hsp = Hs + (size_t)gid * 32 * 32;
    const int aw0 = (tm * 8    ) ^ cA;
    const int aw1 = (tm * 8 + 4) ^ cA;
    const int hw  = (tn * 4    ) ^ cH;

    for (int t = 0; t < T_STEPS; ++t) {
        float xq0 = 0.f, xq1 = 0.f, xq2 = 0.f, xq3 = 0.f;
        if (tid < 128) {
            size_t base = ((size_t)t * 32 + bb + bbt) * 2048 + jb + jj;
            xq0 = __ldcs(&g_xp[base]);
            xq1 = __ldcs(&g_xp[base + 512]);
            xq2 = __ldcs(&g_xp[base + 1024]);
            xq3 = __ldcs(&g_xp[base + 1536]);
        }

        if (t > 0) {
            const float* hsrc = g_hT[t & 1];
            #pragma unroll
            for (int i = 0; i < 8; ++i) {
                int flat = tid + i * 256;
                int q  = flat & 3;
                int kr = flat >> 2;
                float4 v = __ldcg((const float4*)(hsrc + kr * 32 + bb + q * 4));
                *(float4*)(Hs + kr * 32 + ((q * 4) ^ (((kr >> 5) & 1) << 4))) = v;
            }
            __syncthreads();
        }

        u64 acc[4][4];
        #pragma unroll
        for (int i = 0; i < 4; ++i)
            #pragma unroll
            for (int j = 0; j < 4; ++j) acc[i][j] = 0ull;

        #pragma unroll 8
        for (int k = 0; k < 32; ++k) {
            ulonglong2 A0 = *(const ulonglong2*)(wsp + k * 32 + aw0);
            ulonglong2 A1 = *(const ulonglong2*)(wsp + k * 32 + aw1);
            float4 bv     = *(const float4*)    (hsp + k * 32 + hw);
            u64 b0 = pk2(bv.x), b1 = pk2(bv.y), b2 = pk2(bv.z), b3 = pk2(bv.w);
            ffma2(acc[0][0], A0.x, b0, acc[0][0]);
            ffma2(acc[0][1], A0.x, b1, acc[0][1]);
            ffma2(acc[0][2], A0.x, b2, acc[0][2]);
            ffma2(acc[0][3], A0.x, b3, acc[0][3]);
            ffma2(acc[1][0], A0.y, b0, acc[1][0]);
            ffma2(acc[1][1], A0.y, b1, acc[1][1]);
            ffma2(acc[1][2], A0.y, b2, acc[1][2]);
            ffma2(acc[1][3], A0.y, b3, acc[1][3]);
            ffma2(acc[2][0], A1.x, b0, acc[2][0]);
            ffma2(acc[2][1], A1.x, b1, acc[2][1]);
            ffma2(acc[2][2], A1.x, b2, acc[2][2]);
            ffma2(acc[2][3], A1.x, b3, acc[2][3]);
            ffma2(acc[3][0], A1.y, b0, acc[3][0]);
            ffma2(acc[3][1], A1.y, b1, acc[3][1]);
            ffma2(acc[3][2], A1.y, b2, acc[3][2]);
            ffma2(acc[3][3], A1.y, b3, acc[3][3]);
        }

        #pragma unroll
        for (int mp = 0; mp < 4; ++mp)
            #pragma unroll
            for (int n = 0; n < 4; ++n)
                Red[(gid * 16 + tm * 4 + mp) * 17 + (tn * 4 + n)] = acc[mp][n];
        __syncthreads();

        {
            int rp = tid >> 4, b = tid & 15;
            u64 s = Red[rp * 17 + b];
            #pragma unroll
            for (int g = 1; g < 16; ++g)
                fadd2(s, s, Red[(g * 16 + rp) * 17 + b]);
            float2 f = up2(s);
            Gs[(rp * 2    ) * 16 + b] = f.x;
            Gs[(rp * 2 + 1) * 16 + b] = f.y;
        }
        __syncthreads();

        if (tid < 128) {
            const int j = jj, b = bbt;
            float zi = xq0 + Gs[(     j) * 16 + b];
            float zf = xq1 + Gs[( 8 + j) * 16 + b];
            float zg = xq2 + Gs[(16 + j) * 16 + b];
            float zo = xq3 + Gs[(24 + j) * 16 + b];
            float ig = sigfast(zi);
            float fg = sigfast(zf);
            float gg = tanhfast(zg);
            float og = sigfast(zo);
            float cn = fg * Cs[b * 8 + j] + ig * gg;
            Cs[b * 8 + j] = cn;
            float hn = og * tanhfast(cn);

            g_hT[(t + 1) & 1][(jb + j) * 32 + bb + b] = hn;
            out[((size_t)t * 32 + bb + b) * 512 + jb + j] = hn;

            if (t == T_STEPS - 1) {
                long long need = (long long)T_STEPS * BATCH * HID + 2LL * BATCH * HID;
                if (out_size >= need) {
                    size_t ob = (size_t)T_STEPS * BATCH * HID;
                    out[ob + (bb + b) * 512 + jb + j]               = hn;
                    out[ob + BATCH * HID + (bb + b) * 512 + jb + j] = cn;
                }
            }
        }

        if (t < T_STEPS - 1) {
            __threadfence();
            __syncthreads();
            if (tid == 0) {
                atomicAdd(&g_bar2[bg][0], 1u);
                unsigned target = (unsigned)(t + 1) * 64u;
                while (*((volatile unsigned*)&g_bar2[bg][0]) < target) { }
            }
            __syncthreads();
        }
    }
}

// ============================================================================
extern "C" void kernel_launch(void* const* d_in, const int* in_sizes, int n_in,
                              void* d_out, int out_size)
{
    const float* seq = (const float*)d_in[0];
    const float* h0  = (const float*)d_in[1];
    const float* c0  = (const float*)d_in[2];
    const float* Wih = (const float*)d_in[3];
    const float* Whh = (const float*)d_in[4];
    const float* bih = (const float*)d_in[5];
    const float* bhh = (const float*)d_in[6];
    float* out = (float*)d_out;
    (void)in_sizes; (void)n_in;

    // pre-split conversion passes (device scratch referenced inside kernels)
    {
        long long quadsSeq = (long long)T_STEPS * BATCH * 128;   // 8,388,608
        conv_seq_kernel<<<(unsigned)((quadsSeq + 255) / 256), 256>>>(seq);
        long long quadsW = (long long)G4 * 128;                  // 262,144
        conv_wih_kernel<<<(unsigned)((quadsW + 255) / 256), 256>>>(Wih);
    }

    dim3 gA(2048 / 64, (T_STEPS * BATCH) / 128);   // (32, 512)
    xproj_tc_kernel<<<gA, 256>>>(bih, bhh);

    reset_kernel<<<1, 32>>>();

    size_t smem = (size_t)(512 * 32 + 512 * 32 + 512) * sizeof(float)
                + (size_t)(16 * 16 * 17) * sizeof(u64)
                + (size_t)128 * sizeof(float);
    cudaFuncSetAttribute(lstm_rec_kernel,
                         cudaFuncAttributeMaxDynamicSharedMemorySize, (int)smem);
    lstm_rec_kernel<<<128, 256, smem>>>(h0, c0, Whh, out, (long long)out_size);
}

// round 15
// speedup vs baseline: 1.8834x; 1.0080x over previous
#include <cuda_runtime.h>
#include <cuda_bf16.h>
#include <cstdint>

#define T_STEPS 2048
#define BATCH   32
#define INDIM   512
#define HID     512
#define G4      2048   // 4*HID

typedef unsigned long long u64;

// packed f32x2 helpers
__device__ __forceinline__ u64 pk2(float x) {
    u64 r; asm("mov.b64 %0, {%1, %1};" : "=l"(r) : "f"(x)); return r;
}
__device__ __forceinline__ void ffma2(u64& d, u64 a, u64 b, u64 c) {
    asm("fma.rn.f32x2 %0, %1, %2, %3;" : "=l"(d) : "l"(a), "l"(b), "l"(c));
}
__device__ __forceinline__ void fadd2(u64& d, u64 a, u64 b) {
    asm("add.rn.f32x2 %0, %1, %2;" : "=l"(d) : "l"(a), "l"(b));
}
__device__ __forceinline__ float2 up2(u64 v) {
    float2 f; asm("mov.b64 {%0, %1}, %2;" : "=f"(f.x), "=f"(f.y) : "l"(v)); return f;
}
__device__ __forceinline__ float tanhfast(float x) {
    float r; asm("tanh.approx.f32 %0, %1;" : "=f"(r) : "f"(x)); return r;
}
__device__ __forceinline__ float sigfast(float x) {
    return fmaf(tanhfast(0.5f * x), 0.5f, 0.5f);
}

// bf16 mma m16n8k16 (row.col), fp32 accumulate
__device__ __forceinline__ void mma_bf16(float* c,
    uint32_t a0, uint32_t a1, uint32_t a2, uint32_t a3,
    uint32_t b0, uint32_t b1)
{
    asm volatile(
        "mma.sync.aligned.m16n8k16.row.col.f32.bf16.bf16.f32 "
        "{%0,%1,%2,%3},{%4,%5,%6,%7},{%8,%9},{%0,%1,%2,%3};"
        : "+f"(c[0]), "+f"(c[1]), "+f"(c[2]), "+f"(c[3])
        : "r"(a0), "r"(a1), "r"(a2), "r"(a3), "r"(b0), "r"(b1));
}

__device__ __forceinline__ uint32_t packbf(__nv_bfloat16 a, __nv_bfloat16 b) {
    __nv_bfloat162 p = __halves2bfloat162(a, b);
    return *reinterpret_cast<uint32_t*>(&p);
}
__device__ __forceinline__ int phiw(int w) {
    return (w & 8) | ((w & 3) << 1) | ((w >> 2) & 1);
}

// -------- persistent device scratch --------
__device__ float    g_xp[(size_t)T_STEPS * BATCH * G4];   // x_proj[t][b][g]
__device__ float    g_hT[2][HID * BATCH];                 // h transposed: [k][b]
__device__ unsigned g_bar2[2][32];                        // per-batch-group counters

// ============================================================================
// Kernel A (tensor): x_proj = seq @ W_ih^T + bias.
//   bf16 3-split, fp32 accum. 128m x 128n x 32k block tiles (n widened from
//   64 -> 128: halves seq re-load/convert redundancy, doubles MMA per staged
//   byte). 8 warps, each m32 x n64. Fused fp32->bf16 hi/lo split in loader.
// ============================================================================
__global__ __launch_bounds__(256) void xproj_tc_kernel(
    const float* __restrict__ seq,
    const float* __restrict__ Wih,
    const float* __restrict__ bih,
    const float* __restrict__ bhh)
{
    __shared__ uint32_t Ah[128 * 16];
    __shared__ uint32_t Al[128 * 16];
    __shared__ uint32_t Bh[128 * 16];
    __shared__ uint32_t Bl[128 * 16];

    const int tid  = threadIdx.x;
    const int lane = tid & 31;
    const int warp = tid >> 5;
    const int m0g  = blockIdx.y * 128;
    const int n0g  = blockIdx.x * 128;
    const int m0w  = (warp >> 1) * 32;
    const int n0w  = (warp & 1) * 64;
    const int q    = lane & 3;
    const int qr   = lane >> 2;

    float acc[2][8][4];
    #pragma unroll
    for (int i = 0; i < 2; ++i)
        #pragma unroll
        for (int j = 0; j < 8; ++j)
            #pragma unroll
            for (int v = 0; v < 4; ++v) acc[i][j][v] = 0.f;

    for (int kb = 0; kb < 512; kb += 32) {
        // ---- load + split-convert A tile (128 x 32) ----
        #pragma unroll
        for (int i = 0; i < 4; ++i) {
            int flat = tid + i * 256;            // [0,1024)
            int kq = flat & 7;
            int m  = flat >> 3;
            float4 v = *(const float4*)(seq + (size_t)(m0g + m) * 512 + kb + kq * 4);
            __nv_bfloat16 hx = __float2bfloat16_rn(v.x);
            __nv_bfloat16 hy = __float2bfloat16_rn(v.y);
            __nv_bfloat16 hz = __float2bfloat16_rn(v.z);
            __nv_bfloat16 hw = __float2bfloat16_rn(v.w);
            __nv_bfloat16 lx = __float2bfloat16_rn(v.x - __bfloat162float(hx));
            __nv_bfloat16 ly = __float2bfloat16_rn(v.y - __bfloat162float(hy));
            __nv_bfloat16 lz = __float2bfloat16_rn(v.z - __bfloat162float(hz));
            __nv_bfloat16 lw = __float2bfloat16_rn(v.w - __bfloat162float(hw));
            int sw = ((m >> 1) & 1) << 3;
            int p0 = m * 16 + (phiw(2 * kq    ) ^ sw);
            int p1 = m * 16 + (phiw(2 * kq + 1) ^ sw);
            Ah[p0] = packbf(hx, hy);  Al[p0] = packbf(lx, ly);
            Ah[p1] = packbf(hz, hw);  Al[p1] = packbf(lz, lw);
        }
        // ---- load + split-convert B tile (128 x 32) ----
        #pragma unroll
        for (int i = 0; i < 4; ++i) {
            int flat = tid + i * 256;            // [0,1024)
            int kq = flat & 7;
            int n  = flat >> 3;
            float4 v = *(const float4*)(Wih + (size_t)(n0g + n) * 512 + kb + kq * 4);
            __nv_bfloat16 hx = __float2bfloat16_rn(v.x);
            __nv_bfloat16 hy = __float2bfloat16_rn(v.y);
            __nv_bfloat16 hz = __float2bfloat16_rn(v.z);
            __nv_bfloat16 hw = __float2bfloat16_rn(v.w);
            __nv_bfloat16 lx = __float2bfloat16_rn(v.x - __bfloat162float(hx));
            __nv_bfloat16 ly = __float2bfloat16_rn(v.y - __bfloat162float(hy));
            __nv_bfloat16 lz = __float2bfloat16_rn(v.z - __bfloat162float(hz));
            __nv_bfloat16 lw = __float2bfloat16_rn(v.w - __bfloat162float(hw));
            int sw = ((n >> 1) & 1) << 3;
            int p0 = n * 16 + (phiw(2 * kq    ) ^ sw);
            int p1 = n * 16 + (phiw(2 * kq + 1) ^ sw);
            Bh[p0] = packbf(hx, hy);  Bl[p0] = packbf(lx, ly);
            Bh[p1] = packbf(hz, hw);  Bl[p1] = packbf(lz, lw);
        }
        __syncthreads();

        #pragma unroll
        for (int kt = 0; kt < 2; ++kt) {
            const int offBase = (kt << 3) | (q << 1);
            uint32_t ah[2][4], al[2][4];
            #pragma unroll
            for (int tm = 0; tm < 2; ++tm) {
                int r   = m0w + tm * 16 + qr;
                int off = offBase ^ (((r >> 1) & 1) << 3);
                u64 t0 = *(const u64*)(Ah + r * 16 + off);
                u64 t1 = *(const u64*)(Ah + (r + 8) * 16 + off);
                ah[tm][0] = (uint32_t)t0; ah[tm][2] = (uint32_t)(t0 >> 32);
                ah[tm][1] = (uint32_t)t1; ah[tm][3] = (uint32_t)(t1 >> 32);
                u64 s0 = *(const u64*)(Al + r * 16 + off);
                u64 s1 = *(const u64*)(Al + (r + 8) * 16 + off);
                al[tm][0] = (uint32_t)s0; al[tm][2] = (uint32_t)(s0 >> 32);
                al[tm][1] = (uint32_t)s1; al[tm][3] = (uint32_t)(s1 >> 32);
            }
            #pragma unroll
            for (int tn = 0; tn < 8; ++tn) {
                int rn   = n0w + tn * 8 + qr;
                int offb = offBase ^ (((rn >> 1) & 1) << 3);
                u64 hb = *(const u64*)(Bh + rn * 16 + offb);
                u64 lb = *(const u64*)(Bl + rn * 16 + offb);
                uint32_t bh0 = (uint32_t)hb, bh1 = (uint32_t)(hb >> 32);
                uint32_t bl0 = (uint32_t)lb, bl1 = (uint32_t)(lb >> 32);
                #pragma unroll
                for (int tm = 0; tm < 2; ++tm) {
                    mma_bf16(acc[tm][tn], ah[tm][0], ah[tm][1], ah[tm][2], ah[tm][3], bh0, bh1);
                    mma_bf16(acc[tm][tn], ah[tm][0], ah[tm][1], ah[tm][2], ah[tm][3], bl0, bl1);
                    mma_bf16(acc[tm][tn], al[tm][0], al[tm][1], al[tm][2], al[tm][3], bh0, bh1);
                }
            }
        }
        __syncthreads();
    }

    // ---- epilogue: add bias, store fp32 ----
    #pragma unroll
    for (int tn = 0; tn < 8; ++tn) {
        int c0 = n0g + n0w + tn * 8 + q * 2;
        float b0 = bih[c0]     + bhh[c0];
        float b1 = bih[c0 + 1] + bhh[c0 + 1];
        #pragma unroll
        for (int tm = 0; tm < 2; ++tm) {
            int row = m0g + m0w + tm * 16 + qr;
            float2 v0 = make_float2(acc[tm][tn][0] + b0, acc[tm][tn][1] + b1);
            float2 v1 = make_float2(acc[tm][tn][2] + b0, acc[tm][tn][3] + b1);
            __stcs((float2*)(g_xp + (size_t)row * 2048 + c0), v0);
            __stcs((float2*)(g_xp + (size_t)(row + 8) * 2048 + c0), v1);
        }
    }
}

// ============================================================================
__global__ void reset_kernel() {
    if (threadIdx.x < 2) g_bar2[threadIdx.x][0] = 0u;
}

// ============================================================================
// Kernel B: persistent recurrence — EXACT R4/R10 structure (best measured).
// ============================================================================
__global__ __launch_bounds__(256) void lstm_rec_kernel(
    const float* __restrict__ h0,
    const float* __restrict__ c0,
    const float* __restrict__ Whh,
    float* __restrict__ out,
    long long out_size)
{
    extern __shared__ float sm[];
    float* Ws  = sm;                           // 512*32: [k][r], r^(((k>>5)&1)<<2)
    float* Hs  = Ws + 512 * 32;                // 512*32: [k][b], b^(((k>>5)&1)<<4)
    u64*   Red = (u64*)(Hs + 512 * 32);        // 16 groups * 16 r-pairs * 17
    float* Gs  = (float*)(Red + 16 * 16 * 17); // 512
    float* Cs  = Gs + 512;                     // 128

    const int tid = threadIdx.x;
    const int ct  = blockIdx.x;
    const int jg  = ct >> 1;
    const int bg  = ct & 1;
    const int jb  = jg * 8;
    const int bb  = bg * 16;

    for (int idx = tid; idx < 32 * 512; idx += 256) {
        int r = idx & 31, k = idx >> 5;
        int q = r >> 3, j = r & 7;
        float w = Whh[(size_t)(q * 512 + jb + j) * 512 + k];
        Ws[k * 32 + (r ^ (((k >> 5) & 1) << 2))] = w;
    }
    const int jj  = tid & 7;
    const int bbt = tid >> 3;
    if (tid < 128) Cs[bbt * 8 + jj] = c0[(bb + bbt) * 512 + jb + jj];
    for (int idx = tid; idx < 512 * 16; idx += 256) {
        int b = idx & 15, k = idx >> 4;
        Hs[k * 32 + (b ^ (((k >> 5) & 1) << 4))] = h0[(bb + b) * 512 + k];
    }
    __syncthreads();

    const int gid = tid >> 4;
    const int l16 = tid & 15;
    const int tm  = l16 & 3;
    const int tn  = l16 >> 2;
    const int cA  = (gid & 1) << 2;
    const int cH  = (gid & 1) << 4;
    const float* wsp = Ws + (size_t)gid * 32 * 32;
    const float* hsp = Hs + (size_t)gid * 32 * 32;
    const int aw0 = (tm * 8    ) ^ cA;
    const int aw1 = (tm * 8 + 4) ^ cA;
    const int hw  = (tn * 4    ) ^ cH;

    for (int t = 0; t < T_STEPS; ++t) {
        float xq0 = 0.f, xq1 = 0.f, xq2 = 0.f, xq3 = 0.f;
        if (tid < 128) {
            size_t base = ((size_t)t * 32 + bb + bbt) * 2048 + jb + jj;
            xq0 = __ldcs(&g_xp[base]);
            xq1 = __ldcs(&g_xp[base + 512]);
            xq2 = __ldcs(&g_xp[base + 1024]);
            xq3 = __ldcs(&g_xp[base + 1536]);
        }

        if (t > 0) {
            const float* hsrc = g_hT[t & 1];
            #pragma unroll
            for (int i = 0; i < 8; ++i) {
                int flat = tid + i * 256;
                int q  = flat & 3;
                int kr = flat >> 2;
                float4 v = __ldcg((const float4*)(hsrc + kr * 32 + bb + q * 4));
                *(float4*)(Hs + kr * 32 + ((q * 4) ^ (((kr >> 5) & 1) << 4))) = v;
            }
            __syncthreads();
        }

        u64 acc[4][4];
        #pragma unroll
        for (int i = 0; i < 4; ++i)
            #pragma unroll
            for (int j = 0; j < 4; ++j) acc[i][j] = 0ull;

        #pragma unroll 8
        for (int k = 0; k < 32; ++k) {
            ulonglong2 A0 = *(const ulonglong2*)(wsp + k * 32 + aw0);
            ulonglong2 A1 = *(const ulonglong2*)(wsp + k * 32 + aw1);
            float4 bv     = *(const float4*)    (hsp + k * 32 + hw);
            u64 b0 = pk2(bv.x), b1 = pk2(bv.y), b2 = pk2(bv.z), b3 = pk2(bv.w);
            ffma2(acc[0][0], A0.x, b0, acc[0][0]);
            ffma2(acc[0][1], A0.x, b1, acc[0][1]);
            ffma2(acc[0][2], A0.x, b2, acc[0][2]);
            ffma2(acc[0][3], A0.x, b3, acc[0][3]);
            ffma2(acc[1][0], A0.y, b0, acc[1][0]);
            ffma2(acc[1][1], A0.y, b1, acc[1][1]);
            ffma2(acc[1][2], A0.y, b2, acc[1][2]);
            ffma2(acc[1][3], A0.y, b3, acc[1][3]);
            ffma2(acc[2][0], A1.x, b0, acc[2][0]);
            ffma2(acc[2][1], A1.x, b1, acc[2][1]);
            ffma2(acc[2][2], A1.x, b2, acc[2][2]);
            ffma2(acc[2][3], A1.x, b3, acc[2][3]);
            ffma2(acc[3][0], A1.y, b0, acc[3][0]);
            ffma2(acc[3][1], A1.y, b1, acc[3][1]);
            ffma2(acc[3][2], A1.y, b2, acc[3][2]);
            ffma2(acc[3][3], A1.y, b3, acc[3][3]);
        }

        #pragma unroll
        for (int mp = 0; mp < 4; ++mp)
            #pragma unroll
            for (int n = 0; n < 4; ++n)
                Red[(gid * 16 + tm * 4 + mp) * 17 + (tn * 4 + n)] = acc[mp][n];
        __syncthreads();

        {
            int rp = tid >> 4, b = tid & 15;
            u64 s = Red[rp * 17 + b];
            #pragma unroll
            for (int g = 1; g < 16; ++g)
                fadd2(s, s, Red[(g * 16 + rp) * 17 + b]);
            float2 f = up2(s);
            Gs[(rp * 2    ) * 16 + b] = f.x;
            Gs[(rp * 2 + 1) * 16 + b] = f.y;
        }
        __syncthreads();

        if (tid < 128) {
            const int j = jj, b = bbt;
            float zi = xq0 + Gs[(     j) * 16 + b];
            float zf = xq1 + Gs[( 8 + j) * 16 + b];
            float zg = xq2 + Gs[(16 + j) * 16 + b];
            float zo = xq3 + Gs[(24 + j) * 16 + b];
            float ig = sigfast(zi);
            float fg = sigfast(zf);
            float gg = tanhfast(zg);
            float og = sigfast(zo);
            float cn = fg * Cs[b * 8 + j] + ig * gg;
            Cs[b * 8 + j] = cn;
            float hn = og * tanhfast(cn);

            g_hT[(t + 1) & 1][(jb + j) * 32 + bb + b] = hn;
            out[((size_t)t * 32 + bb + b) * 512 + jb + j] = hn;

            if (t == T_STEPS - 1) {
                long long need = (long long)T_STEPS * BATCH * HID + 2LL * BATCH * HID;
                if (out_size >= need) {
                    size_t ob = (size_t)T_STEPS * BATCH * HID;
                    out[ob + (bb + b) * 512 + jb + j]               = hn;
                    out[ob + BATCH * HID + (bb + b) * 512 + jb + j] = cn;
                }
            }
        }

        if (t < T_STEPS - 1) {
            __threadfence();
            __syncthreads();
            if (tid == 0) {
                atomicAdd(&g_bar2[bg][0], 1u);
                unsigned target = (unsigned)(t + 1) * 64u;
                while (*((volatile unsigned*)&g_bar2[bg][0]) < target) { }
            }
            __syncthreads();
        }
    }
}

// ============================================================================
extern "C" void kernel_launch(void* const* d_in, const int* in_sizes, int n_in,
                              void* d_out, int out_size)
{
    const float* seq = (const float*)d_in[0];
    const float* h0  = (const float*)d_in[1];
    const float* c0  = (const float*)d_in[2];
    const float* Wih = (const float*)d_in[3];
    const float* Whh = (const float*)d_in[4];
    const float* bih = (const float*)d_in[5];
    const float* bhh = (const float*)d_in[6];
    float* out = (float*)d_out;
    (void)in_sizes; (void)n_in;

    dim3 gA(2048 / 128, (T_STEPS * BATCH) / 128);   // (16, 512)
    xproj_tc_kernel<<<gA, 256>>>(seq, Wih, bih, bhh);

    reset_kernel<<<1, 32>>>();

    size_t smem = (size_t)(512 * 32 + 512 * 32 + 512) * sizeof(float)
                + (size_t)(16 * 16 * 17) * sizeof(u64)
                + (size_t)128 * sizeof(float);
    cudaFuncSetAttribute(lstm_rec_kernel,
                         cudaFuncAttributeMaxDynamicSharedMemorySize, (int)smem);
    lstm_rec_kernel<<<128, 256, smem>>>(h0, c0, Whh, out, (long long)out_size);
}